// round 16
// baseline (speedup 1.0000x reference)
#include <cuda_runtime.h>
#include <cuda_fp16.h>
#include <cuda_bf16.h>
#include <cstdint>

#define BATCH 2
#define CDIM 64
#define CQ 8
#define NVOX 8000
#define MT 32
#define NT 64
#define NTILES 125
#define MTILES 250
#define ATHREADS 128
#define HALF0 63              // tiles [0,63) | [63,125)

__device__ __align__(16) __half g_qh[BATCH * NVOX * CQ];
__device__ __align__(16) __half g_kh[BATCH * NVOX * CQ];
__device__ __align__(16) __nv_bfloat16 g_vb[BATCH * NVOX * CDIM];
// per-(b,mtile,half) partial: O[32][64] + rs[32] = 2080 floats
__device__ __align__(16) float g_pO[BATCH * MTILES * 2 * 2080];
__device__ int g_flag[BATCH * MTILES];

// ---------------------------------------------------------------------------
__device__ __forceinline__ uint32_t smem_u32(const void* p) {
    uint32_t a;
    asm("{ .reg .u64 t; cvta.to.shared.u64 t, %1; cvt.u32.u64 %0, t; }" : "=r"(a) : "l"(p));
    return a;
}
__device__ __forceinline__ float ex2f(float x) {
    float y; asm("ex2.approx.ftz.f32 %0, %1;" : "=f"(y) : "f"(x)); return y;
}
__device__ __forceinline__ uint32_t packbf16(float hi, float lo) {
    uint32_t d; asm("cvt.rn.bf16x2.f32 %0, %1, %2;" : "=r"(d) : "f"(hi), "f"(lo));
    return d;
}
__device__ __forceinline__ void cp16(uint32_t dst, const void* src) {
    asm volatile("cp.async.cg.shared.global [%0], [%1], 16;"
                 :: "r"(dst), "l"(__cvta_generic_to_global(src)) : "memory");
}
#define CP_COMMIT() asm volatile("cp.async.commit_group;" ::: "memory")
#define CP_WAIT2()  asm volatile("cp.async.wait_group 2;" ::: "memory")

__device__ __forceinline__ void mma8_f16(float* c, uint32_t a0, uint32_t a1, uint32_t b) {
    asm volatile(
        "mma.sync.aligned.m16n8k8.row.col.f32.f16.f16.f32 "
        "{%0,%1,%2,%3}, {%4,%5}, {%6}, {%0,%1,%2,%3};"
        : "+f"(c[0]), "+f"(c[1]), "+f"(c[2]), "+f"(c[3])
        : "r"(a0), "r"(a1), "r"(b));
}
__device__ __forceinline__ void mma16_bf16(float* c, const uint32_t* a, uint32_t b0, uint32_t b1) {
    asm volatile(
        "mma.sync.aligned.m16n8k16.row.col.f32.bf16.bf16.f32 "
        "{%0,%1,%2,%3}, {%4,%5,%6,%7}, {%8,%9}, {%0,%1,%2,%3};"
        : "+f"(c[0]), "+f"(c[1]), "+f"(c[2]), "+f"(c[3])
        : "r"(a[0]), "r"(a[1]), "r"(a[2]), "r"(a[3]), "r"(b0), "r"(b1));
}

// ---------------------------------------------------------------------------
// Kernel 1: qkv projections, z-split; also zeroes the merge flags each launch
// ---------------------------------------------------------------------------
__global__ void __launch_bounds__(128) qkv_kernel(
    const float* __restrict__ x,
    const float* __restrict__ wq, const float* __restrict__ bq,
    const float* __restrict__ wk, const float* __restrict__ bk,
    const float* __restrict__ wv, const float* __restrict__ bv)
{
    __shared__ float sw[CDIM * 36];

    const int tid = threadIdx.x;
    const int b = blockIdx.y;
    const int z = blockIdx.z;
    const int n0 = blockIdx.x * 256 + tid;
    const int n1 = n0 + 128;
    const bool ok0 = n0 < NVOX, ok1 = n1 < NVOX;
    const int c0i = ok0 ? n0 : 0, c1i = ok1 ? n1 : 0;
    const float* xb = x + (size_t)b * CDIM * NVOX;
    const float L2E = 1.4426950408889634f;

    // zero merge flags (before attn kernel runs; same stream ordering)
    if (z == 0 && b == 0) {
        int i = blockIdx.x * 128 + tid;
        if (i < BATCH * MTILES) g_flag[i] = 0;
    }

    if (z == 0) {
        for (int i = tid; i < CQ * CDIM; i += 128) {
            int j = i >> 6, c = i & 63;
            sw[c * 8 + j] = wq[i];
            sw[512 + c * 8 + j] = wk[i];
        }
        __syncthreads();

        float qa0[CQ], ka0[CQ], qa1[CQ], ka1[CQ];
#pragma unroll
        for (int j = 0; j < CQ; j++) {
            float bqv = bq[j], bkv = bk[j];
            qa0[j] = bqv; qa1[j] = bqv; ka0[j] = bkv; ka1[j] = bkv;
        }
#pragma unroll 4
        for (int c = 0; c < CDIM; c++) {
            float x0 = xb[(size_t)c * NVOX + c0i];
            float x1 = xb[(size_t)c * NVOX + c1i];
            const float4* wq4 = (const float4*)(sw + c * 8);
            const float4* wk4 = (const float4*)(sw + 512 + c * 8);
#pragma unroll
            for (int h = 0; h < 2; h++) {
                float4 a = wq4[h], bb = wk4[h];
                qa0[h*4+0] += a.x * x0; qa0[h*4+1] += a.y * x0;
                qa0[h*4+2] += a.z * x0; qa0[h*4+3] += a.w * x0;
                qa1[h*4+0] += a.x * x1; qa1[h*4+1] += a.y * x1;
                qa1[h*4+2] += a.z * x1; qa1[h*4+3] += a.w * x1;
                ka0[h*4+0] += bb.x * x0; ka0[h*4+1] += bb.y * x0;
                ka0[h*4+2] += bb.z * x0; ka0[h*4+3] += bb.w * x0;
                ka1[h*4+0] += bb.x * x1; ka1[h*4+1] += bb.y * x1;
                ka1[h*4+2] += bb.z * x1; ka1[h*4+3] += bb.w * x1;
            }
        }
        if (ok0) {
            size_t qo4 = ((size_t)b * NVOX + n0) * 4;
#pragma unroll
            for (int jj = 0; jj < 4; jj++) {
                ((__half2*)g_qh)[qo4 + jj] = __floats2half2_rn(qa0[2*jj] * L2E, qa0[2*jj+1] * L2E);
                ((__half2*)g_kh)[qo4 + jj] = __floats2half2_rn(ka0[2*jj], ka0[2*jj+1]);
            }
        }
        if (ok1) {
            size_t qo4 = ((size_t)b * NVOX + n1) * 4;
#pragma unroll
            for (int jj = 0; jj < 4; jj++) {
                ((__half2*)g_qh)[qo4 + jj] = __floats2half2_rn(qa1[2*jj] * L2E, qa1[2*jj+1] * L2E);
                ((__half2*)g_kh)[qo4 + jj] = __floats2half2_rn(ka1[2*jj], ka1[2*jj+1]);
            }
        }
    } else {
        const int off = (z - 1) * 32;
        for (int i = tid; i < 32 * CDIM; i += 128) {
            int v = i >> 6, c = i & 63;
            sw[c * 36 + v] = wv[(off + v) * CDIM + c];
        }
        __syncthreads();

        float a0[32], a1[32];
#pragma unroll
        for (int j = 0; j < 32; j++) { float bb = bv[off + j]; a0[j] = bb; a1[j] = bb; }
#pragma unroll 2
        for (int c = 0; c < CDIM; c++) {
            float x0 = xb[(size_t)c * NVOX + c0i];
            float x1 = xb[(size_t)c * NVOX + c1i];
            const float4* wv4 = (const float4*)(sw + c * 36);
#pragma unroll
            for (int vv = 0; vv < 8; vv++) {
                float4 w = wv4[vv];
                a0[vv*4+0] += w.x * x0; a0[vv*4+1] += w.y * x0;
                a0[vv*4+2] += w.z * x0; a0[vv*4+3] += w.w * x0;
                a1[vv*4+0] += w.x * x1; a1[vv*4+1] += w.y * x1;
                a1[vv*4+2] += w.z * x1; a1[vv*4+3] += w.w * x1;
            }
        }
        if (ok0) {
            int T = n0 >> 6, kk = n0 & 63;
            int blk = kk >> 4, j2 = (kk & 15) >> 1, par = kk & 1;
            int pos = (j2 < 4) ? 2 * j2 : 2 * (j2 - 4) + 1;
            size_t base = ((((size_t)b * NTILES + T) * 4 + blk) * 64) * 16 + pos * 2 + par;
#pragma unroll
            for (int j = 0; j < 32; j++)
                g_vb[base + (size_t)(off + j) * 16] = __float2bfloat16_rn(a0[j]);
        }
        if (ok1) {
            int T = n1 >> 6, kk = n1 & 63;
            int blk = kk >> 4, j2 = (kk & 15) >> 1, par = kk & 1;
            int pos = (j2 < 4) ? 2 * j2 : 2 * (j2 - 4) + 1;
            size_t base = ((((size_t)b * NTILES + T) * 4 + blk) * 64) * 16 + pos * 2 + par;
#pragma unroll
            for (int j = 0; j < 32; j++)
                g_vb[base + (size_t)(off + j) * 16] = __float2bfloat16_rn(a1[j]);
        }
    }
}

// ---------------------------------------------------------------------------
// Kernel 2: key-split flash attention (blockIdx.z = key half), 20 HMMA/tile.
// Main loop identical to the best 79.9us kernel; each CTA handles ~62 tiles.
// Partials merged via fence + atomic flag: second-arriving CTA combines and
// writes the final output (single commutative f32 add => deterministic).
// ---------------------------------------------------------------------------
__global__ void __launch_bounds__(ATHREADS, 4) attn_kernel(
    const float* __restrict__ x, const float* __restrict__ gamma,
    float* __restrict__ out)
{
    extern __shared__ char SB[];
    const uint32_t SBu = smem_u32(SB);

    const int tid = threadIdx.x;
    const int nw = tid >> 5;
    const int lane = tid & 31;
    const int g = lane >> 2;
    const int tq = lane & 3;
    const int b = blockIdx.y;
    const int kz = blockIdx.z;
    const int mbase = blockIdx.x * MT;
    const int t0 = kz ? HALF0 : 0;
    const int t1 = kz ? NTILES : HALF0;

    uint32_t qa[2][2];
#pragma unroll
    for (int mf = 0; mf < 2; mf++)
#pragma unroll
        for (int i = 0; i < 2; i++) {
            int row = mbase + mf * 16 + i * 8 + g;
            qa[mf][i] = *reinterpret_cast<const uint32_t*>(
                (const char*)g_qh + ((size_t)b * NVOX + row) * 16 + tq * 4);
        }

    float Oa[2][8][4];
#pragma unroll
    for (int mf = 0; mf < 2; mf++)
#pragma unroll
        for (int cf = 0; cf < 8; cf++)
#pragma unroll
            for (int j = 0; j < 4; j++) Oa[mf][cf][j] = 0.f;
    float psacc[2][2] = {{0.f, 0.f}, {0.f, 0.f}};

    auto prefetch = [&](int tile, int st) {
        uint32_t base = SBu + (uint32_t)st * 9216u + (uint32_t)nw * 2304u;
        if (lane < 16) {
            const char* ksrc = (const char*)g_kh +
                ((size_t)b * NVOX + (size_t)tile * NT + nw * 16) * 16;
            cp16(base + lane * 16, ksrc + lane * 16);
        }
        const char* vsrc = (const char*)g_vb +
            (((size_t)b * NTILES + tile) * 8192) + nw * 2048;
#pragma unroll
        for (int j = 0; j < 4; j++)
            cp16(base + 256 + lane * 16 + j * 512, vsrc + lane * 16 + j * 512);
    };

    const float NSHL = -28.853900817779268f;   // -20 * log2(e)

    prefetch(t0, 0); CP_COMMIT();
    prefetch(t0 + 1, 1); CP_COMMIT();
    prefetch(t0 + 2, 2); CP_COMMIT();

    int s = 0;
    for (int t = t0; t < t1; t++) {
        CP_WAIT2();

        const char* wbase = SB + s * 9216 + nw * 2304;
        const float2* vq = reinterpret_cast<const float2*>(wbase + 256);

        uint32_t ap[2][4];
#pragma unroll
        for (int half = 0; half < 2; half++) {
            uint32_t kb = *reinterpret_cast<const uint32_t*>(
                wbase + ((half * 8 + g) << 4) + (tq << 2));
#pragma unroll
            for (int mf = 0; mf < 2; mf++) {
                float yv[4] = {NSHL, NSHL, NSHL, NSHL};
                mma8_f16(yv, qa[mf][0], qa[mf][1], kb);
                float p0 = ex2f(yv[0]);
                float p1 = ex2f(yv[1]);
                float p2 = ex2f(yv[2]);
                float p3 = ex2f(yv[3]);
                psacc[mf][0] += p0 + p1;
                psacc[mf][1] += p2 + p3;
                ap[mf][half * 2 + 0] = packbf16(p1, p0);
                ap[mf][half * 2 + 1] = packbf16(p3, p2);
            }
        }

#pragma unroll
        for (int cf = 0; cf < 8; cf++) {
            float2 w = vq[(cf * 8 + g) * 4 + tq];
            uint32_t vb0 = __float_as_uint(w.x), vb1 = __float_as_uint(w.y);
            mma16_bf16(Oa[0][cf], ap[0], vb0, vb1);
            mma16_bf16(Oa[1][cf], ap[1], vb0, vb1);
        }

        if (t + 3 < t1) prefetch(t + 3, (s + 3) & 3);
        CP_COMMIT();
        s = (s + 1) & 3;
    }

    // ---- row sums: shfl reduce over tq lanes ----
    float* rsum = reinterpret_cast<float*>(SB + 36864);   // [4][32]
#pragma unroll
    for (int mf = 0; mf < 2; mf++)
#pragma unroll
        for (int hh = 0; hh < 2; hh++) {
            float v = psacc[mf][hh];
            v += __shfl_xor_sync(0xFFFFFFFFu, v, 1);
            v += __shfl_xor_sync(0xFFFFFFFFu, v, 2);
            if (tq == 0) rsum[nw * 32 + mf * 16 + hh * 8 + g] = v;
        }
    __syncthreads();

    // ---- combine O quarters through smem, 4 phases ----
    float* Osm = reinterpret_cast<float*>(SB);            // [32][66]
#pragma unroll 1
    for (int ph = 0; ph < 4; ph++) {
        if (nw == ph) {
#pragma unroll
            for (int mf = 0; mf < 2; mf++) {
                int r0 = mf * 16 + g;
#pragma unroll
                for (int cf = 0; cf < 8; cf++) {
                    int c0 = cf * 8 + 2 * tq;
                    if (ph == 0) {
                        Osm[r0 * 66 + c0]           = Oa[mf][cf][0];
                        Osm[r0 * 66 + c0 + 1]       = Oa[mf][cf][1];
                        Osm[(r0 + 8) * 66 + c0]     = Oa[mf][cf][2];
                        Osm[(r0 + 8) * 66 + c0 + 1] = Oa[mf][cf][3];
                    } else {
                        Osm[r0 * 66 + c0]           += Oa[mf][cf][0];
                        Osm[r0 * 66 + c0 + 1]       += Oa[mf][cf][1];
                        Osm[(r0 + 8) * 66 + c0]     += Oa[mf][cf][2];
                        Osm[(r0 + 8) * 66 + c0 + 1] += Oa[mf][cf][3];
                    }
                }
            }
        }
        __syncthreads();
    }

    // ---- write my partial (O[32][64] + rs[32]) to scratch ----
    const int slotIdx = b * MTILES + blockIdx.x;
    float* slot = g_pO + ((size_t)slotIdx * 2 + kz) * 2080;
#pragma unroll
    for (int it = 0; it < 4; it++) {
        int idx = tid + it * 128;          // 512 float4 = 2048 floats
        int m = idx >> 4, c4 = (idx & 15) * 4;
        float4 v = make_float4(Osm[m * 66 + c4], Osm[m * 66 + c4 + 1],
                               Osm[m * 66 + c4 + 2], Osm[m * 66 + c4 + 3]);
        *reinterpret_cast<float4*>(slot + m * 64 + c4) = v;
    }
    if (tid < 32)
        slot[2048 + tid] = rsum[tid] + rsum[32 + tid] + rsum[64 + tid] + rsum[96 + tid];
    __threadfence();

    __shared__ int s_old;
    if (tid == 0) s_old = atomicAdd(&g_flag[slotIdx], 1);
    __syncthreads();
    if (s_old == 0) return;          // first finisher: partial stays in scratch
    __threadfence();                 // acquire: peer's writes now visible

    // ---- second finisher: merge with peer and write final output ----
    const float* peer = g_pO + ((size_t)slotIdx * 2 + (kz ^ 1)) * 2080;
    const int m = tid & 31;
    const float rs = rsum[m] + rsum[32 + m] + rsum[64 + m] + rsum[96 + m]
                   + peer[2048 + m];
    const float scl = gamma[0] / rs;
#pragma unroll 1
    for (int it = 0; it < 16; it++) {
        int c = it * 4 + (tid >> 5);
        size_t gi = ((size_t)(b * CDIM + c)) * NVOX + mbase + m;
        out[gi] = (Osm[m * 66 + c] + peer[m * 64 + c]) * scl + x[gi];
    }
}

// ---------------------------------------------------------------------------
extern "C" void kernel_launch(void* const* d_in, const int* in_sizes, int n_in,
                              void* d_out, int out_size)
{
    const float* x     = (const float*)d_in[0];
    const float* wq    = (const float*)d_in[1];
    const float* bq    = (const float*)d_in[2];
    const float* wk    = (const float*)d_in[3];
    const float* bk    = (const float*)d_in[4];
    const float* wv    = (const float*)d_in[5];
    const float* bv    = (const float*)d_in[6];
    const float* gamma = (const float*)d_in[7];
    float* out = (float*)d_out;

    dim3 qgrid(32, BATCH, 3);
    qkv_kernel<<<qgrid, 128>>>(x, wq, bq, wk, bk, wv, bv);

    int smem_bytes = 37376;   // 4*9216 + 512 (rsum)
    cudaFuncSetAttribute(attn_kernel, cudaFuncAttributeMaxDynamicSharedMemorySize,
                         smem_bytes);
    cudaFuncSetAttribute(attn_kernel, cudaFuncAttributePreferredSharedMemoryCarveout,
                         100);
    dim3 agrid(MTILES, BATCH, 2);
    attn_kernel<<<agrid, ATHREADS, smem_bytes>>>(x, gamma, out);
}

// round 17
// speedup vs baseline: 1.1795x; 1.1795x over previous
#include <cuda_runtime.h>
#include <cuda_fp16.h>
#include <cuda_bf16.h>
#include <cstdint>

#define BATCH 2
#define CDIM 64
#define CQ 8
#define NVOX 8000
#define MT 32
#define NT 64
#define NTILES 125
#define MTILES 250
#define ATHREADS 128

__device__ __align__(16) __half g_qh[BATCH * NVOX * CQ];
__device__ __align__(16) __half g_kh[BATCH * NVOX * CQ];
__device__ __align__(16) __nv_bfloat16 g_vb[BATCH * NVOX * CDIM];

// ---------------------------------------------------------------------------
__device__ __forceinline__ uint32_t smem_u32(const void* p) {
    uint32_t a;
    asm("{ .reg .u64 t; cvta.to.shared.u64 t, %1; cvt.u32.u64 %0, t; }" : "=r"(a) : "l"(p));
    return a;
}
__device__ __forceinline__ float ex2f(float x) {
    float y; asm("ex2.approx.ftz.f32 %0, %1;" : "=f"(y) : "f"(x)); return y;
}
__device__ __forceinline__ uint32_t packbf16(float hi, float lo) {
    uint32_t d; asm("cvt.rn.bf16x2.f32 %0, %1, %2;" : "=r"(d) : "f"(hi), "f"(lo));
    return d;
}
__device__ __forceinline__ void cp16(uint32_t dst, const void* src) {
    asm volatile("cp.async.cg.shared.global [%0], [%1], 16;"
                 :: "r"(dst), "l"(__cvta_generic_to_global(src)) : "memory");
}
#define CP_COMMIT() asm volatile("cp.async.commit_group;" ::: "memory")
#define CP_WAIT2()  asm volatile("cp.async.wait_group 2;" ::: "memory")

__device__ __forceinline__ void mma8_f16(float* c, uint32_t a0, uint32_t a1, uint32_t b) {
    asm volatile(
        "mma.sync.aligned.m16n8k8.row.col.f32.f16.f16.f32 "
        "{%0,%1,%2,%3}, {%4,%5}, {%6}, {%0,%1,%2,%3};"
        : "+f"(c[0]), "+f"(c[1]), "+f"(c[2]), "+f"(c[3])
        : "r"(a0), "r"(a1), "r"(b));
}
__device__ __forceinline__ void mma16_bf16(float* c, const uint32_t* a, uint32_t b0, uint32_t b1) {
    asm volatile(
        "mma.sync.aligned.m16n8k16.row.col.f32.bf16.bf16.f32 "
        "{%0,%1,%2,%3}, {%4,%5,%6,%7}, {%8,%9}, {%0,%1,%2,%3};"
        : "+f"(c[0]), "+f"(c[1]), "+f"(c[2]), "+f"(c[3])
        : "r"(a[0]), "r"(a[1]), "r"(a[2]), "r"(a[3]), "r"(b0), "r"(b1));
}

// ---------------------------------------------------------------------------
// Kernel 1: qkv projections, z-split (z=0: q,k | z=1: v[0:32) | z=2: v[32:64))
// ---------------------------------------------------------------------------
__global__ void __launch_bounds__(128) qkv_kernel(
    const float* __restrict__ x,
    const float* __restrict__ wq, const float* __restrict__ bq,
    const float* __restrict__ wk, const float* __restrict__ bk,
    const float* __restrict__ wv, const float* __restrict__ bv)
{
    __shared__ float sw[CDIM * 36];

    const int tid = threadIdx.x;
    const int b = blockIdx.y;
    const int z = blockIdx.z;
    const int n0 = blockIdx.x * 256 + tid;
    const int n1 = n0 + 128;
    const bool ok0 = n0 < NVOX, ok1 = n1 < NVOX;
    const int c0i = ok0 ? n0 : 0, c1i = ok1 ? n1 : 0;
    const float* xb = x + (size_t)b * CDIM * NVOX;
    const float L2E = 1.4426950408889634f;

    if (z == 0) {
        for (int i = tid; i < CQ * CDIM; i += 128) {
            int j = i >> 6, c = i & 63;
            sw[c * 8 + j] = wq[i];
            sw[512 + c * 8 + j] = wk[i];
        }
        __syncthreads();

        float qa0[CQ], ka0[CQ], qa1[CQ], ka1[CQ];
#pragma unroll
        for (int j = 0; j < CQ; j++) {
            float bqv = bq[j], bkv = bk[j];
            qa0[j] = bqv; qa1[j] = bqv; ka0[j] = bkv; ka1[j] = bkv;
        }
#pragma unroll 4
        for (int c = 0; c < CDIM; c++) {
            float x0 = xb[(size_t)c * NVOX + c0i];
            float x1 = xb[(size_t)c * NVOX + c1i];
            const float4* wq4 = (const float4*)(sw + c * 8);
            const float4* wk4 = (const float4*)(sw + 512 + c * 8);
#pragma unroll
            for (int h = 0; h < 2; h++) {
                float4 a = wq4[h], bb = wk4[h];
                qa0[h*4+0] += a.x * x0; qa0[h*4+1] += a.y * x0;
                qa0[h*4+2] += a.z * x0; qa0[h*4+3] += a.w * x0;
                qa1[h*4+0] += a.x * x1; qa1[h*4+1] += a.y * x1;
                qa1[h*4+2] += a.z * x1; qa1[h*4+3] += a.w * x1;
                ka0[h*4+0] += bb.x * x0; ka0[h*4+1] += bb.y * x0;
                ka0[h*4+2] += bb.z * x0; ka0[h*4+3] += bb.w * x0;
                ka1[h*4+0] += bb.x * x1; ka1[h*4+1] += bb.y * x1;
                ka1[h*4+2] += bb.z * x1; ka1[h*4+3] += bb.w * x1;
            }
        }
        if (ok0) {
            size_t qo4 = ((size_t)b * NVOX + n0) * 4;
#pragma unroll
            for (int jj = 0; jj < 4; jj++) {
                ((__half2*)g_qh)[qo4 + jj] = __floats2half2_rn(qa0[2*jj] * L2E, qa0[2*jj+1] * L2E);
                ((__half2*)g_kh)[qo4 + jj] = __floats2half2_rn(ka0[2*jj], ka0[2*jj+1]);
            }
        }
        if (ok1) {
            size_t qo4 = ((size_t)b * NVOX + n1) * 4;
#pragma unroll
            for (int jj = 0; jj < 4; jj++) {
                ((__half2*)g_qh)[qo4 + jj] = __floats2half2_rn(qa1[2*jj] * L2E, qa1[2*jj+1] * L2E);
                ((__half2*)g_kh)[qo4 + jj] = __floats2half2_rn(ka1[2*jj], ka1[2*jj+1]);
            }
        }
    } else {
        const int off = (z - 1) * 32;
        for (int i = tid; i < 32 * CDIM; i += 128) {
            int v = i >> 6, c = i & 63;
            sw[c * 36 + v] = wv[(off + v) * CDIM + c];
        }
        __syncthreads();

        float a0[32], a1[32];
#pragma unroll
        for (int j = 0; j < 32; j++) { float bb = bv[off + j]; a0[j] = bb; a1[j] = bb; }
#pragma unroll 2
        for (int c = 0; c < CDIM; c++) {
            float x0 = xb[(size_t)c * NVOX + c0i];
            float x1 = xb[(size_t)c * NVOX + c1i];
            const float4* wv4 = (const float4*)(sw + c * 36);
#pragma unroll
            for (int vv = 0; vv < 8; vv++) {
                float4 w = wv4[vv];
                a0[vv*4+0] += w.x * x0; a0[vv*4+1] += w.y * x0;
                a0[vv*4+2] += w.z * x0; a0[vv*4+3] += w.w * x0;
                a1[vv*4+0] += w.x * x1; a1[vv*4+1] += w.y * x1;
                a1[vv*4+2] += w.z * x1; a1[vv*4+3] += w.w * x1;
            }
        }
        if (ok0) {
            int T = n0 >> 6, kk = n0 & 63;
            int blk = kk >> 4, j2 = (kk & 15) >> 1, par = kk & 1;
            int pos = (j2 < 4) ? 2 * j2 : 2 * (j2 - 4) + 1;
            size_t base = ((((size_t)b * NTILES + T) * 4 + blk) * 64) * 16 + pos * 2 + par;
#pragma unroll
            for (int j = 0; j < 32; j++)
                g_vb[base + (size_t)(off + j) * 16] = __float2bfloat16_rn(a0[j]);
        }
        if (ok1) {
            int T = n1 >> 6, kk = n1 & 63;
            int blk = kk >> 4, j2 = (kk & 15) >> 1, par = kk & 1;
            int pos = (j2 < 4) ? 2 * j2 : 2 * (j2 - 4) + 1;
            size_t base = ((((size_t)b * NTILES + T) * 4 + blk) * 64) * 16 + pos * 2 + par;
#pragma unroll
            for (int j = 0; j < 32; j++)
                g_vb[base + (size_t)(off + j) * 16] = __float2bfloat16_rn(a1[j]);
        }
    }
}

// ---------------------------------------------------------------------------
// Kernel 2: barrier-free flash attention, 20 HMMA/warp/tile (best R15 loop),
// with a FLAT epilogue: 2 barriers total instead of 5, no serialized phases.
// After the loop each warp dumps its O partial into its own smem region
// (stage buffers are dead), then all threads merge the 4 regions in parallel.
// SMEM: 4 stages x 9216B; epilogue regions Osm[nw][32][66] @ 0; rsum @ 36864.
// ---------------------------------------------------------------------------
__global__ void __launch_bounds__(ATHREADS, 4) attn_kernel(
    const float* __restrict__ x, const float* __restrict__ gamma,
    float* __restrict__ out)
{
    extern __shared__ char SB[];
    const uint32_t SBu = smem_u32(SB);

    const int tid = threadIdx.x;
    const int nw = tid >> 5;
    const int lane = tid & 31;
    const int g = lane >> 2;
    const int tq = lane & 3;
    const int b = blockIdx.y;
    const int mbase = blockIdx.x * MT;

    uint32_t qa[2][2];
#pragma unroll
    for (int mf = 0; mf < 2; mf++)
#pragma unroll
        for (int i = 0; i < 2; i++) {
            int row = mbase + mf * 16 + i * 8 + g;
            qa[mf][i] = *reinterpret_cast<const uint32_t*>(
                (const char*)g_qh + ((size_t)b * NVOX + row) * 16 + tq * 4);
        }

    float Oa[2][8][4];
#pragma unroll
    for (int mf = 0; mf < 2; mf++)
#pragma unroll
        for (int cf = 0; cf < 8; cf++)
#pragma unroll
            for (int j = 0; j < 4; j++) Oa[mf][cf][j] = 0.f;
    float psacc[2][2] = {{0.f, 0.f}, {0.f, 0.f}};

    auto prefetch = [&](int tile, int st) {
        uint32_t base = SBu + (uint32_t)st * 9216u + (uint32_t)nw * 2304u;
        if (lane < 16) {
            const char* ksrc = (const char*)g_kh +
                ((size_t)b * NVOX + (size_t)tile * NT + nw * 16) * 16;
            cp16(base + lane * 16, ksrc + lane * 16);
        }
        const char* vsrc = (const char*)g_vb +
            (((size_t)b * NTILES + tile) * 8192) + nw * 2048;
#pragma unroll
        for (int j = 0; j < 4; j++)
            cp16(base + 256 + lane * 16 + j * 512, vsrc + lane * 16 + j * 512);
    };

    const float NSHL = -28.853900817779268f;   // -20 * log2(e)

    prefetch(0, 0); CP_COMMIT();
    prefetch(1, 1); CP_COMMIT();
    prefetch(2, 2); CP_COMMIT();

    int s = 0;
    for (int t = 0; t < NTILES; t++) {
        CP_WAIT2();   // stage s (tile t) resident

        const char* wbase = SB + s * 9216 + nw * 2304;
        const float2* vq = reinterpret_cast<const float2*>(wbase + 256);

        uint32_t ap[2][4];
#pragma unroll
        for (int half = 0; half < 2; half++) {
            uint32_t kb = *reinterpret_cast<const uint32_t*>(
                wbase + ((half * 8 + g) << 4) + (tq << 2));
#pragma unroll
            for (int mf = 0; mf < 2; mf++) {
                float yv[4] = {NSHL, NSHL, NSHL, NSHL};
                mma8_f16(yv, qa[mf][0], qa[mf][1], kb);
                float p0 = ex2f(yv[0]);
                float p1 = ex2f(yv[1]);
                float p2 = ex2f(yv[2]);
                float p3 = ex2f(yv[3]);
                psacc[mf][0] += p0 + p1;
                psacc[mf][1] += p2 + p3;
                ap[mf][half * 2 + 0] = packbf16(p1, p0);
                ap[mf][half * 2 + 1] = packbf16(p3, p2);
            }
        }

#pragma unroll
        for (int cf = 0; cf < 8; cf++) {
            float2 w = vq[(cf * 8 + g) * 4 + tq];
            uint32_t vb0 = __float_as_uint(w.x), vb1 = __float_as_uint(w.y);
            mma16_bf16(Oa[0][cf], ap[0], vb0, vb1);
            mma16_bf16(Oa[1][cf], ap[1], vb0, vb1);
        }

        if (t + 3 < NTILES) prefetch(t + 3, (s + 3) & 3);
        CP_COMMIT();
        s = (s + 1) & 3;
    }

    // ---- row sums: shfl reduce over tq lanes, store to rsum (outside stages)
    float* rsum = reinterpret_cast<float*>(SB + 36864);   // [4][32]
#pragma unroll
    for (int mf = 0; mf < 2; mf++)
#pragma unroll
        for (int hh = 0; hh < 2; hh++) {
            float v = psacc[mf][hh];
            v += __shfl_xor_sync(0xFFFFFFFFu, v, 1);
            v += __shfl_xor_sync(0xFFFFFFFFu, v, 2);
            if (tq == 0) rsum[nw * 32 + mf * 16 + hh * 8 + g] = v;
        }

    // barrier 1: all warps done with stage buffers (and rsum written)
    __syncthreads();

    // ---- each warp dumps its O partial into its own region (parallel) ----
    float* Osm = reinterpret_cast<float*>(SB) + nw * 2112;   // [32][66] per warp
#pragma unroll
    for (int mf = 0; mf < 2; mf++) {
        int r0 = mf * 16 + g;
#pragma unroll
        for (int cf = 0; cf < 8; cf++) {
            int c0 = cf * 8 + 2 * tq;
            *reinterpret_cast<float2*>(&Osm[r0 * 66 + c0]) =
                make_float2(Oa[mf][cf][0], Oa[mf][cf][1]);
            *reinterpret_cast<float2*>(&Osm[(r0 + 8) * 66 + c0]) =
                make_float2(Oa[mf][cf][2], Oa[mf][cf][3]);
        }
    }

    // barrier 2: regions complete
    __syncthreads();

    // ---- merge 4 regions + scaled residual store, fully parallel ----
    const float* O0 = reinterpret_cast<const float*>(SB);
    const int m = tid & 31;
    const float rs = rsum[m] + rsum[32 + m] + rsum[64 + m] + rsum[96 + m];
    const float scl = gamma[0] / rs;
#pragma unroll 1
    for (int it = 0; it < 16; it++) {
        int c = it * 4 + (tid >> 5);
        int o = m * 66 + c;
        float v = O0[o] + O0[2112 + o] + O0[4224 + o] + O0[6336 + o];
        size_t gi = ((size_t)(b * CDIM + c)) * NVOX + mbase + m;
        out[gi] = v * scl + x[gi];
    }
}

// ---------------------------------------------------------------------------
extern "C" void kernel_launch(void* const* d_in, const int* in_sizes, int n_in,
                              void* d_out, int out_size)
{
    const float* x     = (const float*)d_in[0];
    const float* wq    = (const float*)d_in[1];
    const float* bq    = (const float*)d_in[2];
    const float* wk    = (const float*)d_in[3];
    const float* bk    = (const float*)d_in[4];
    const float* wv    = (const float*)d_in[5];
    const float* bv    = (const float*)d_in[6];
    const float* gamma = (const float*)d_in[7];
    float* out = (float*)d_out;

    dim3 qgrid(32, BATCH, 3);
    qkv_kernel<<<qgrid, 128>>>(x, wq, bq, wk, bk, wv, bv);

    int smem_bytes = 37376;   // 4*9216 + 512 (rsum)
    cudaFuncSetAttribute(attn_kernel, cudaFuncAttributeMaxDynamicSharedMemorySize,
                         smem_bytes);
    cudaFuncSetAttribute(attn_kernel, cudaFuncAttributePreferredSharedMemoryCarveout,
                         100);
    dim3 agrid(MTILES, BATCH);
    attn_kernel<<<agrid, ATHREADS, smem_bytes>>>(x, gamma, out);
}